// round 2
// baseline (speedup 1.0000x reference)
#include <cuda_runtime.h>
#include <cuda_bf16.h>

#define L 2048
#define LMASK 2047
#define LSHIFT 11
// allowed class-code pairs (codes 0..3 -> bases 2,3,5,7): {0,3},{1,2},{2,3} both orders
#define PAIRMASK 0x5A48u

// ---------------- device scratch (static globals; no allocation) ----------------
__device__ float d_C[(size_t)L * L];          // compacted active x active matrix
__device__ unsigned long long d_best[L];      // per-vertex / per-local-row best priority
__device__ int d_cls[L];                      // base class per position
__device__ int d_act[L];                      // active vertex list (ascending)
__device__ int d_nAct;

// global priority: value desc, flat index (a*L+b, a<b) asc
__device__ __forceinline__ unsigned long long pack_g(float s, int a, int b) {
    unsigned k = (unsigned)(a * L + b);
    return ((unsigned long long)__float_as_uint(s) << 32) |
           (unsigned long long)(~k);
}
// local priority: same order restricted to active set (active list ascending =>
// local lexicographic order == global lexicographic order)
__device__ __forceinline__ unsigned long long pack_l(float s, int lo, int hi) {
    unsigned k = ((unsigned)lo << LSHIFT) | (unsigned)hi;
    return ((unsigned long long)__float_as_uint(s) << 32) |
           (unsigned long long)(~k);
}

// ---------------- K1: classes + clear best ----------------
__global__ void kern_cls(const float* __restrict__ feat) {
    int i = blockIdx.x * blockDim.x + threadIdx.x;
    if (i >= L) return;
    float f0 = feat[(size_t)i * L];
    float f1 = feat[(size_t)L * L + (size_t)i * L];
    float f2 = feat[2 * (size_t)L * L + (size_t)i * L];
    float f3 = feat[3 * (size_t)L * L + (size_t)i * L];
    int c = 0; float m = f0;
    if (f1 > m) { m = f1; c = 1; }
    if (f2 > m) { m = f2; c = 2; }
    if (f3 > m) { m = f3; c = 3; }
    d_cls[i] = c;
    d_best[i] = 0ULL;
}

// ---------------- K2: round-1 per-vertex best + zero output (no S matrix) ----------------
__global__ void kern_build(const float* __restrict__ con, float* __restrict__ out) {
    int bi = blockIdx.y, bj = blockIdx.x;
    if (bj < bi) return;   // upper-triangle tiles only (uniform per block)

    __shared__ float sB[32][33];
    __shared__ unsigned long long sP[32][33];
    __shared__ int clsR[32], clsC[32];

    int tx = threadIdx.x, ty = threadIdx.y;
    int i = bi * 32 + ty;
    int j = bj * 32 + tx;

    if (ty == 0) { clsR[tx] = d_cls[bi * 32 + tx]; clsC[tx] = d_cls[bj * 32 + tx]; }

    float a = con[(size_t)i * L + j];                               // tile (bi,bj)
    sB[ty][tx] = con[(size_t)(bj * 32 + ty) * L + (bi * 32 + tx)];  // tile (bj,bi)
    __syncthreads();

    float b = sB[tx][ty];          // con[j][i]
    float v = 0.5f * (a + b);
    int d = j - i;
    bool band = (d >= 4) || (d <= -4);
    bool pm = (PAIRMASK >> ((clsR[ty] << 2) | clsC[tx])) & 1u;
    float s = (band && pm) ? v : 0.0f;

    // fused output zeroing (replaces memset): both tiles, coalesced
    out[(size_t)i * L + j] = 0.0f;
    out[(size_t)(bj * 32 + ty) * L + (bi * 32 + tx)] = 0.0f;

    unsigned long long p = 0ULL;
    if (s > 0.0f && j > i) p = pack_g(s, i, j);
    sP[ty][tx] = p;
    __syncthreads();

    // row max (vertex i)
    unsigned long long m = p;
    #pragma unroll
    for (int o = 16; o; o >>= 1) {
        unsigned long long q = __shfl_xor_sync(0xFFFFFFFFu, m, o);
        if (q > m) m = q;
    }
    if (tx == 0 && m) atomicMax(&d_best[i], m);

    // col max (vertex j = bj*32 + ty)
    unsigned long long cm = sP[tx][ty];
    #pragma unroll
    for (int o = 16; o; o >>= 1) {
        unsigned long long q = __shfl_xor_sync(0xFFFFFFFFu, cm, o);
        if (q > cm) cm = q;
    }
    if (tx == 0 && cm) atomicMax(&d_best[bj * 32 + ty], cm);
}

// ---------------- K3: round-1 take, write output, build active list ----------------
__global__ void kern_take1(float* __restrict__ out) {
    __shared__ int wsum[32];
    __shared__ int sTotal;
    int t = threadIdx.x;
    int lane = t & 31, wid = t >> 5;

    int f[2]; int vv[2];
    #pragma unroll
    for (int r = 0; r < 2; r++) {
        int v = 2 * t + r;
        int fl = 0;
        unsigned long long b = d_best[v];
        if (b) {
            unsigned k = ~((unsigned)b);
            int i = (int)(k >> LSHIFT), j = (int)(k & LMASK);
            int u = (v == i) ? j : i;
            if (d_best[u] == b) {
                if (v == i) {   // write once per pair
                    float val = __uint_as_float((unsigned)(b >> 32));
                    out[i * L + j] = val;
                    out[j * L + i] = val;
                }
            } else fl = 1;      // survives
        }
        f[r] = fl; vv[r] = v;
    }

    int sum = f[0] + f[1];
    int x = sum;
    #pragma unroll
    for (int o = 1; o < 32; o <<= 1) { int y = __shfl_up_sync(0xFFFFFFFFu, x, o); if (lane >= o) x += y; }
    if (lane == 31) wsum[wid] = x;
    __syncthreads();
    if (wid == 0) {
        int z = wsum[lane];
        #pragma unroll
        for (int o = 1; o < 32; o <<= 1) { int y = __shfl_up_sync(0xFFFFFFFFu, z, o); if (lane >= o) z += y; }
        wsum[lane] = z;
        if (lane == 31) sTotal = z;
    }
    __syncthreads();
    int ex = (wid ? wsum[wid - 1] : 0) + x - sum;
    if (f[0]) d_act[ex] = vv[0];
    if (f[1]) d_act[ex + f[0]] = vv[1];
    if (t == 0) d_nAct = sTotal;
}

// ---------------- K4: gather compacted C (active x active) + fused round-2 best ----------------
__global__ void kern_compact(const float* __restrict__ con) {
    __shared__ int sAct[L];
    __shared__ int sCls[L];
    int n = d_nAct;
    if (n == 0) return;
    int stride = (n + 31) & ~31;

    for (int t = threadIdx.x; t < n; t += blockDim.x) {
        int v = d_act[t];
        sAct[t] = v;
        sCls[t] = d_cls[v];
    }
    __syncthreads();

    int lane = threadIdx.x & 31;
    int gw = (blockIdx.x * blockDim.x + threadIdx.x) >> 5;
    int tw = (gridDim.x * blockDim.x) >> 5;

    for (int a = gw; a < n; a += tw) {
        int va = sAct[a];
        int ca = sCls[a];
        const float* __restrict__ rowA = con + (size_t)va * L;
        float* __restrict__ rowC = d_C + (size_t)a * stride;
        unsigned long long m = 0ULL;
        for (int b = lane; b < n; b += 32) {
            int vb = sAct[b];
            float x = rowA[vb];
            float y = con[(size_t)vb * L + va];
            float v = 0.5f * (x + y);
            int d = va - vb;
            bool band = (d >= 4) || (d <= -4);
            bool pm = (PAIRMASK >> ((ca << 2) | sCls[b])) & 1u;
            float s = (band && pm) ? v : 0.0f;
            rowC[b] = s;                       // coalesced
            if (s > 0.0f) {
                unsigned long long p = (a < b) ? pack_l(s, a, b) : pack_l(s, b, a);
                if (p > m) m = p;
            }
        }
        #pragma unroll
        for (int o = 16; o; o >>= 1) {
            unsigned long long q = __shfl_xor_sync(0xFFFFFFFFu, m, o);
            if (q > m) m = q;
        }
        if (lane == 0) d_best[a] = m;          // local-indexed round-2 best
    }
}

// ---------------- K5: persistent single block — all remaining rounds on C ----------------
__global__ void kern_finish(float* __restrict__ out) {
    __shared__ int sG[L];                      // local -> global id
    __shared__ int sCur[L];                    // current local ids
    __shared__ int sTmp[L];
    __shared__ unsigned long long sBest[L];    // indexed by local id
    __shared__ int wsum[32];
    __shared__ int sTotal;

    int t = threadIdx.x;                       // 1024 threads
    int lane = t & 31, wid = t >> 5;
    int n0 = d_nAct;
    int stride = (n0 + 31) & ~31;

    for (int x = t; x < n0; x += 1024) {
        sG[x] = d_act[x];
        sBest[x] = d_best[x];
        sCur[x] = x;
    }
    __syncthreads();

    int n = n0;
    while (n > 0) {
        // ---- take: mutual-best edges over sCur ----
        int f[2]; int vv[2];
        #pragma unroll
        for (int r = 0; r < 2; r++) {
            int idx = 2 * t + r;
            int fl = 0, la = -1;
            if (idx < n) {
                la = sCur[idx];
                unsigned long long b = sBest[la];
                if (b) {
                    unsigned k = ~((unsigned)b);
                    int lo = (int)(k >> LSHIFT), hi = (int)(k & LMASK);
                    int lu = (la == lo) ? hi : lo;
                    if (sBest[lu] == b) {
                        if (la == lo) {
                            float val = __uint_as_float((unsigned)(b >> 32));
                            int gi = sG[lo], gj = sG[hi];
                            out[gi * L + gj] = val;
                            out[gj * L + gi] = val;
                        }
                    } else fl = 1;
                }
            }
            f[r] = fl; vv[r] = la;
        }

        // ---- compact survivors ----
        int sum = f[0] + f[1];
        int x = sum;
        #pragma unroll
        for (int o = 1; o < 32; o <<= 1) { int y = __shfl_up_sync(0xFFFFFFFFu, x, o); if (lane >= o) x += y; }
        if (lane == 31) wsum[wid] = x;
        __syncthreads();
        if (wid == 0) {
            int z = wsum[lane];
            #pragma unroll
            for (int o = 1; o < 32; o <<= 1) { int y = __shfl_up_sync(0xFFFFFFFFu, z, o); if (lane >= o) z += y; }
            wsum[lane] = z;
            if (lane == 31) sTotal = z;
        }
        __syncthreads();
        int ex = (wid ? wsum[wid - 1] : 0) + x - sum;
        if (f[0]) sTmp[ex] = vv[0];
        if (f[1]) sTmp[ex + f[0]] = vv[1];
        __syncthreads();
        int nn = sTotal;
        for (int x2 = t; x2 < nn; x2 += 1024) sCur[x2] = sTmp[x2];
        __syncthreads();
        n = nn;
        if (n == 0) break;

        // ---- recompute best over current set (warp per row, L2-resident C) ----
        for (int ai = wid; ai < n; ai += 32) {
            int la = sCur[ai];
            const float* __restrict__ row = d_C + (size_t)la * stride;
            unsigned long long m = 0ULL;
            for (int li = lane; li < n; li += 32) {
                int lb = sCur[li];
                float s = row[lb];
                if (s > 0.0f) {
                    unsigned long long p = (la < lb) ? pack_l(s, la, lb) : pack_l(s, lb, la);
                    if (p > m) m = p;
                }
            }
            #pragma unroll
            for (int o = 16; o; o >>= 1) {
                unsigned long long q = __shfl_xor_sync(0xFFFFFFFFu, m, o);
                if (q > m) m = q;
            }
            if (lane == 0) sBest[la] = m;
        }
        __syncthreads();
    }
}

// ---------------- launch ----------------
extern "C" void kernel_launch(void* const* d_in, const int* in_sizes, int n_in,
                              void* d_out, int out_size) {
    const float* con  = (const float*)d_in[0];
    const float* feat = (const float*)d_in[1];
    if (n_in >= 2 && in_sizes[0] > in_sizes[1]) {   // feat (8L^2) is the bigger input
        const float* tmp = con; con = feat; feat = tmp;
    }
    float* out = (float*)d_out;

    kern_cls<<<2, 1024>>>(feat);

    dim3 gb(L / 32, L / 32), tb(32, 32);
    kern_build<<<gb, tb>>>(con, out);        // round-1 best + output zeroing fused

    kern_take1<<<1, 1024>>>(out);            // round 1 take -> d_act

    kern_compact<<<64, 512>>>(con);          // gather C + round-2 best fused

    kern_finish<<<1, 1024>>>(out);           // all remaining rounds on C
}

// round 3
// speedup vs baseline: 1.0200x; 1.0200x over previous
#include <cuda_runtime.h>
#include <cuda_bf16.h>

#define L 2048
#define LMASK 2047
#define LSHIFT 11
// allowed class-code pairs (codes 0..3 -> bases 2,3,5,7): {0,3},{1,2},{2,3} both orders
#define PAIRMASK 0x5A48u

// ---------------- device scratch (static globals; no allocation) ----------------
__device__ float d_C[(size_t)L * L];          // compacted active x active matrix
__device__ unsigned long long d_best[L];      // per-vertex / per-local-row best priority
__device__ int d_cls[L];                      // base class per position
__device__ int d_act[L];                      // active vertex list (ascending)
__device__ int d_nAct;

// global priority: value desc, flat index (a*L+b, a<b) asc
__device__ __forceinline__ unsigned long long pack_g(float s, int a, int b) {
    unsigned k = (unsigned)(a * L + b);
    return ((unsigned long long)__float_as_uint(s) << 32) |
           (unsigned long long)(~k);
}
// local priority: same order restricted to active set (active list ascending =>
// local lexicographic order == global lexicographic order)
__device__ __forceinline__ unsigned long long pack_l(float s, int lo, int hi) {
    unsigned k = ((unsigned)lo << LSHIFT) | (unsigned)hi;
    return ((unsigned long long)__float_as_uint(s) << 32) |
           (unsigned long long)(~k);
}

__device__ __forceinline__ unsigned long long warp_max(unsigned long long m) {
    #pragma unroll
    for (int o = 16; o; o >>= 1) {
        unsigned long long q = __shfl_xor_sync(0xFFFFFFFFu, m, o);
        if (q > m) m = q;
    }
    return m;
}

// ---------------- K1: classes + clear best ----------------
__global__ void kern_cls(const float* __restrict__ feat) {
    int i = blockIdx.x * blockDim.x + threadIdx.x;
    if (i >= L) return;
    float f0 = feat[(size_t)i * L];
    float f1 = feat[(size_t)L * L + (size_t)i * L];
    float f2 = feat[2 * (size_t)L * L + (size_t)i * L];
    float f3 = feat[3 * (size_t)L * L + (size_t)i * L];
    int c = 0; float m = f0;
    if (f1 > m) { m = f1; c = 1; }
    if (f2 > m) { m = f2; c = 2; }
    if (f3 > m) { m = f3; c = 3; }
    d_cls[i] = c;
    d_best[i] = 0ULL;
}

// ---------------- K2: round-1 per-vertex best + zero output (no S matrix) ----------------
__global__ void kern_build(const float* __restrict__ con, float* __restrict__ out) {
    int bi = blockIdx.y, bj = blockIdx.x;
    if (bj < bi) return;   // upper-triangle tiles only (uniform per block)

    __shared__ float sB[32][33];
    __shared__ unsigned long long sP[32][33];
    __shared__ int clsR[32], clsC[32];

    int tx = threadIdx.x, ty = threadIdx.y;
    int i = bi * 32 + ty;
    int j = bj * 32 + tx;

    if (ty == 0) { clsR[tx] = d_cls[bi * 32 + tx]; clsC[tx] = d_cls[bj * 32 + tx]; }

    float a = con[(size_t)i * L + j];                               // tile (bi,bj)
    sB[ty][tx] = con[(size_t)(bj * 32 + ty) * L + (bi * 32 + tx)];  // tile (bj,bi)
    __syncthreads();

    float b = sB[tx][ty];          // con[j][i]
    float v = 0.5f * (a + b);
    int d = j - i;
    bool band = (d >= 4) || (d <= -4);
    bool pm = (PAIRMASK >> ((clsR[ty] << 2) | clsC[tx])) & 1u;
    float s = (band && pm) ? v : 0.0f;

    // fused output zeroing (replaces memset): both tiles, coalesced
    out[(size_t)i * L + j] = 0.0f;
    out[(size_t)(bj * 32 + ty) * L + (bi * 32 + tx)] = 0.0f;

    unsigned long long p = 0ULL;
    if (s > 0.0f && j > i) p = pack_g(s, i, j);
    sP[ty][tx] = p;
    __syncthreads();

    // row max (vertex i)
    unsigned long long m = warp_max(p);
    if (tx == 0 && m) atomicMax(&d_best[i], m);

    // col max (vertex j = bj*32 + ty)
    unsigned long long cm = warp_max(sP[tx][ty]);
    if (tx == 0 && cm) atomicMax(&d_best[bj * 32 + ty], cm);
}

// ---------------- K3: round-1 take, write output, build active list, clear best ----------------
__global__ void kern_take1(float* __restrict__ out) {
    __shared__ int wsum[32];
    __shared__ int sTotal;
    int t = threadIdx.x;
    int lane = t & 31, wid = t >> 5;

    int f[2]; int vv[2];
    #pragma unroll
    for (int r = 0; r < 2; r++) {
        int v = 2 * t + r;
        int fl = 0;
        unsigned long long b = d_best[v];
        if (b) {
            unsigned k = ~((unsigned)b);
            int i = (int)(k >> LSHIFT), j = (int)(k & LMASK);
            int u = (v == i) ? j : i;
            if (d_best[u] == b) {
                if (v == i) {   // write once per pair
                    float val = __uint_as_float((unsigned)(b >> 32));
                    out[i * L + j] = val;
                    out[j * L + i] = val;
                }
            } else fl = 1;      // survives
        }
        f[r] = fl; vv[r] = v;
    }

    int sum = f[0] + f[1];
    int x = sum;
    #pragma unroll
    for (int o = 1; o < 32; o <<= 1) { int y = __shfl_up_sync(0xFFFFFFFFu, x, o); if (lane >= o) x += y; }
    if (lane == 31) wsum[wid] = x;
    __syncthreads();
    if (wid == 0) {
        int z = wsum[lane];
        #pragma unroll
        for (int o = 1; o < 32; o <<= 1) { int y = __shfl_up_sync(0xFFFFFFFFu, z, o); if (lane >= o) z += y; }
        wsum[lane] = z;
        if (lane == 31) sTotal = z;
    }
    __syncthreads();
    int ex = (wid ? wsum[wid - 1] : 0) + x - sum;
    if (f[0]) d_act[ex] = vv[0];
    if (f[1]) d_act[ex + f[0]] = vv[1];
    if (t == 0) d_nAct = sTotal;

    // clear best for compact's local-index atomicMax (all reads of d_best are
    // before the first __syncthreads above)
    d_best[2 * t] = 0ULL;
    d_best[2 * t + 1] = 0ULL;
}

// ---------------- K4: tiled gather of C (active x active) + fused round-2 best ----------------
// All global reads are row-local gathers (never cross-row scatter); transpose via smem.
__global__ void kern_compact(const float* __restrict__ con) {
    int n = d_nAct;
    int bi = blockIdx.y, bj = blockIdx.x;
    if (bj < bi || bi * 32 >= n || bj * 32 >= n) return;
    int ns = (n + 31) & ~31;

    __shared__ float sT[32][33];               // transpose staging
    __shared__ unsigned long long sP[32][33];
    __shared__ int gA[32], gB[32], cA[32], cB[32];

    int tx = threadIdx.x, ty = threadIdx.y;
    if (ty == 0) {
        int a = bi * 32 + tx;
        int va = (a < n) ? d_act[a] : -1;
        gA[tx] = va; cA[tx] = (va >= 0) ? d_cls[va] : 0;
        int b = bj * 32 + tx;
        int vb = (b < n) ? d_act[b] : -1;
        gB[tx] = vb; cB[tx] = (vb >= 0) ? d_cls[vb] : 0;
    }
    __syncthreads();

    int va = gA[ty], vb = gB[tx];
    float x = (va >= 0 && vb >= 0) ? con[(size_t)va * L + vb] : 0.0f;   // row va gather
    int vy = gB[ty], vxa = gA[tx];
    sT[ty][tx] = (vy >= 0 && vxa >= 0) ? con[(size_t)vy * L + vxa] : 0.0f; // row vb gather
    __syncthreads();

    float v = 0.5f * (x + sT[tx][ty]);         // con[va][vb] + con[vb][va]
    int a = bi * 32 + ty, b = bj * 32 + tx;
    float s = 0.0f;
    unsigned long long p = 0ULL;
    if (va >= 0 && vb >= 0) {
        int d = va - vb;
        bool band = (d >= 4) || (d <= -4);
        bool pm = (PAIRMASK >> ((cA[ty] << 2) | cB[tx])) & 1u;
        s = (band && pm) ? v : 0.0f;
        if (s > 0.0f && b > a) p = pack_l(s, a, b);
    }
    if (a < n && b < n) d_C[(size_t)a * ns + b] = s;
    __syncthreads();
    sT[ty][tx] = s;                             // reuse for transpose write
    sP[ty][tx] = p;
    __syncthreads();

    int a2 = bj * 32 + ty, b2 = bi * 32 + tx;   // transposed tile, coalesced
    if (a2 < n && b2 < n) d_C[(size_t)a2 * ns + b2] = sT[tx][ty];

    unsigned long long m = warp_max(p);                 // row max -> vertex a
    if (tx == 0 && m) atomicMax(&d_best[a], m);
    unsigned long long cm = warp_max(sP[tx][ty]);       // col max -> vertex bj*32+ty
    if (tx == 0 && cm) atomicMax(&d_best[bj * 32 + ty], cm);
}

// ---------------- K5: persistent single block — take round 2, then all rounds on C ----------------
__global__ void kern_finish(float* __restrict__ out) {
    __shared__ int sG[L];                      // local -> global id
    __shared__ int sCur[L];                    // current local ids
    __shared__ int sTmp[L];
    __shared__ unsigned long long sBest[L];    // indexed by local id
    __shared__ int wsum[32];
    __shared__ int sTotal;

    int t = threadIdx.x;                       // 1024 threads
    int lane = t & 31, wid = t >> 5;
    int n0 = d_nAct;
    int ns = (n0 + 31) & ~31;

    for (int x = t; x < n0; x += 1024) {
        sG[x] = d_act[x];
        sBest[x] = d_best[x];                  // round-2 best from compact
        sCur[x] = x;
    }
    __syncthreads();

    int n = n0;
    while (n > 0) {
        // ---- take: mutual-best edges over sCur ----
        int f[2]; int vv[2];
        #pragma unroll
        for (int r = 0; r < 2; r++) {
            int idx = 2 * t + r;
            int fl = 0, la = -1;
            if (idx < n) {
                la = sCur[idx];
                unsigned long long b = sBest[la];
                if (b) {
                    unsigned k = ~((unsigned)b);
                    int lo = (int)(k >> LSHIFT), hi = (int)(k & LMASK);
                    int lu = (la == lo) ? hi : lo;
                    if (sBest[lu] == b) {
                        if (la == lo) {
                            float val = __uint_as_float((unsigned)(b >> 32));
                            int gi = sG[lo], gj = sG[hi];
                            out[gi * L + gj] = val;
                            out[gj * L + gi] = val;
                        }
                    } else fl = 1;
                }
            }
            f[r] = fl; vv[r] = la;
        }

        // ---- compact survivors ----
        int sum = f[0] + f[1];
        int x = sum;
        #pragma unroll
        for (int o = 1; o < 32; o <<= 1) { int y = __shfl_up_sync(0xFFFFFFFFu, x, o); if (lane >= o) x += y; }
        if (lane == 31) wsum[wid] = x;
        __syncthreads();
        if (wid == 0) {
            int z = wsum[lane];
            #pragma unroll
            for (int o = 1; o < 32; o <<= 1) { int y = __shfl_up_sync(0xFFFFFFFFu, z, o); if (lane >= o) z += y; }
            wsum[lane] = z;
            if (lane == 31) sTotal = z;
        }
        __syncthreads();
        int ex = (wid ? wsum[wid - 1] : 0) + x - sum;
        if (f[0]) sTmp[ex] = vv[0];
        if (f[1]) sTmp[ex + f[0]] = vv[1];
        __syncthreads();
        int nn = sTotal;
        for (int x2 = t; x2 < nn; x2 += 1024) sCur[x2] = sTmp[x2];
        __syncthreads();
        n = nn;
        if (n == 0) break;

        // ---- recompute best over current set (warp per row, L2-resident C) ----
        for (int ai = wid; ai < n; ai += 32) {
            int la = sCur[ai];
            const float* __restrict__ row = d_C + (size_t)la * ns;
            unsigned long long m = 0ULL;
            for (int li = lane; li < n; li += 32) {
                int lb = sCur[li];
                float s = row[lb];
                if (s > 0.0f) {
                    unsigned long long p = (la < lb) ? pack_l(s, la, lb) : pack_l(s, lb, la);
                    if (p > m) m = p;
                }
            }
            m = warp_max(m);
            if (lane == 0) sBest[la] = m;
        }
        __syncthreads();
    }
}

// ---------------- launch ----------------
extern "C" void kernel_launch(void* const* d_in, const int* in_sizes, int n_in,
                              void* d_out, int out_size) {
    const float* con  = (const float*)d_in[0];
    const float* feat = (const float*)d_in[1];
    if (n_in >= 2 && in_sizes[0] > in_sizes[1]) {   // feat (8L^2) is the bigger input
        const float* tmp = con; con = feat; feat = tmp;
    }
    float* out = (float*)d_out;

    kern_cls<<<2, 1024>>>(feat);

    dim3 gb(L / 32, L / 32), tb(32, 32);
    kern_build<<<gb, tb>>>(con, out);        // round-1 best + output zeroing fused

    kern_take1<<<1, 1024>>>(out);            // round 1 take -> d_act, clears d_best

    kern_compact<<<gb, tb>>>(con);           // tiled gather of C + round-2 best fused

    kern_finish<<<1, 1024>>>(out);           // take round 2, then all remaining rounds
}

// round 4
// speedup vs baseline: 3.4854x; 3.4170x over previous
#include <cuda_runtime.h>
#include <cuda_bf16.h>

#define L 2048
#define LMASK 2047
#define LSHIFT 11
// allowed class-code pairs (codes 0..3 -> bases 2,3,5,7): {0,3},{1,2},{2,3} both orders
#define PAIRMASK 0x5A48u

// ---------------- device scratch (static globals; no allocation) ----------------
__device__ float d_C[(size_t)L * L];          // compacted active x active matrix
__device__ unsigned long long d_best[L];      // per-vertex / per-local-row best priority
__device__ int d_cls[L];                      // base class per position
__device__ int d_act[L];                      // active vertex list after round 1 (ascending, global ids)
__device__ int d_nAct;
__device__ int d_lact[2][L];                  // ping-pong local-id active lists
__device__ int d_nL[2];

// global priority: value desc, flat index (a*L+b, a<b) asc
__device__ __forceinline__ unsigned long long pack_g(float s, int a, int b) {
    unsigned k = (unsigned)(a * L + b);
    return ((unsigned long long)__float_as_uint(s) << 32) |
           (unsigned long long)(~k);
}
// local priority: same order restricted to active set (active list ascending =>
// local lexicographic order == global lexicographic order)
__device__ __forceinline__ unsigned long long pack_l(float s, int lo, int hi) {
    unsigned k = ((unsigned)lo << LSHIFT) | (unsigned)hi;
    return ((unsigned long long)__float_as_uint(s) << 32) |
           (unsigned long long)(~k);
}

__device__ __forceinline__ unsigned long long warp_max(unsigned long long m) {
    #pragma unroll
    for (int o = 16; o; o >>= 1) {
        unsigned long long q = __shfl_xor_sync(0xFFFFFFFFu, m, o);
        if (q > m) m = q;
    }
    return m;
}

// ---------------- K1: classes + clear best ----------------
__global__ void kern_cls(const float* __restrict__ feat) {
    int i = blockIdx.x * blockDim.x + threadIdx.x;
    if (i >= L) return;
    float f0 = feat[(size_t)i * L];
    float f1 = feat[(size_t)L * L + (size_t)i * L];
    float f2 = feat[2 * (size_t)L * L + (size_t)i * L];
    float f3 = feat[3 * (size_t)L * L + (size_t)i * L];
    int c = 0; float m = f0;
    if (f1 > m) { m = f1; c = 1; }
    if (f2 > m) { m = f2; c = 2; }
    if (f3 > m) { m = f3; c = 3; }
    d_cls[i] = c;
    d_best[i] = 0ULL;
}

// ---------------- K2: round-1 per-vertex best + zero output ----------------
__global__ void kern_build(const float* __restrict__ con, float* __restrict__ out) {
    int bi = blockIdx.y, bj = blockIdx.x;
    if (bj < bi) return;   // upper-triangle tiles only (uniform per block)

    __shared__ float sB[32][33];
    __shared__ unsigned long long sP[32][33];
    __shared__ int clsR[32], clsC[32];

    int tx = threadIdx.x, ty = threadIdx.y;
    int i = bi * 32 + ty;
    int j = bj * 32 + tx;

    if (ty == 0) { clsR[tx] = d_cls[bi * 32 + tx]; clsC[tx] = d_cls[bj * 32 + tx]; }

    float a = con[(size_t)i * L + j];                               // tile (bi,bj)
    sB[ty][tx] = con[(size_t)(bj * 32 + ty) * L + (bi * 32 + tx)];  // tile (bj,bi)
    __syncthreads();

    float b = sB[tx][ty];          // con[j][i]
    float v = 0.5f * (a + b);
    int d = j - i;
    bool band = (d >= 4) || (d <= -4);
    bool pm = (PAIRMASK >> ((clsR[ty] << 2) | clsC[tx])) & 1u;
    float s = (band && pm) ? v : 0.0f;

    // fused output zeroing (replaces memset): both tiles, coalesced
    out[(size_t)i * L + j] = 0.0f;
    out[(size_t)(bj * 32 + ty) * L + (bi * 32 + tx)] = 0.0f;

    unsigned long long p = 0ULL;
    if (s > 0.0f && j > i) p = pack_g(s, i, j);
    sP[ty][tx] = p;
    __syncthreads();

    // row max (vertex i)
    unsigned long long m = warp_max(p);
    if (tx == 0 && m) atomicMax(&d_best[i], m);

    // col max (vertex j = bj*32 + ty)
    unsigned long long cm = warp_max(sP[tx][ty]);
    if (tx == 0 && cm) atomicMax(&d_best[bj * 32 + ty], cm);
}

// ---------------- K3: round-1 take (global space), build d_act, clear best ----------------
__global__ void kern_take1(float* __restrict__ out) {
    __shared__ int wsum[32];
    __shared__ int sTotal;
    int t = threadIdx.x;
    int lane = t & 31, wid = t >> 5;

    int f[2]; int vv[2];
    #pragma unroll
    for (int r = 0; r < 2; r++) {
        int v = 2 * t + r;
        int fl = 0;
        unsigned long long b = d_best[v];
        if (b) {
            unsigned k = ~((unsigned)b);
            int i = (int)(k >> LSHIFT), j = (int)(k & LMASK);
            int u = (v == i) ? j : i;
            if (d_best[u] == b) {
                if (v == i) {   // write once per pair
                    float val = __uint_as_float((unsigned)(b >> 32));
                    out[i * L + j] = val;
                    out[j * L + i] = val;
                }
            } else fl = 1;      // survives
        }
        f[r] = fl; vv[r] = v;
    }

    int sum = f[0] + f[1];
    int x = sum;
    #pragma unroll
    for (int o = 1; o < 32; o <<= 1) { int y = __shfl_up_sync(0xFFFFFFFFu, x, o); if (lane >= o) x += y; }
    if (lane == 31) wsum[wid] = x;
    __syncthreads();
    if (wid == 0) {
        int z = wsum[lane];
        #pragma unroll
        for (int o = 1; o < 32; o <<= 1) { int y = __shfl_up_sync(0xFFFFFFFFu, z, o); if (lane >= o) z += y; }
        wsum[lane] = z;
        if (lane == 31) sTotal = z;
    }
    __syncthreads();
    int ex = (wid ? wsum[wid - 1] : 0) + x - sum;
    if (f[0]) d_act[ex] = vv[0];
    if (f[1]) d_act[ex + f[0]] = vv[1];
    if (t == 0) d_nAct = sTotal;

    // clear best for compact's local-index atomicMax (all d_best reads are above)
    d_best[2 * t] = 0ULL;
    d_best[2 * t + 1] = 0ULL;
}

// ---------------- K4: tiled gather of C (active x active) + fused round-2 best ----------------
__global__ void kern_compact(const float* __restrict__ con) {
    int n = d_nAct;
    int bi = blockIdx.y, bj = blockIdx.x;
    if (bj < bi || bi * 32 >= n || bj * 32 >= n) return;
    int ns = (n + 31) & ~31;

    __shared__ float sT[32][33];               // transpose staging
    __shared__ unsigned long long sP[32][33];
    __shared__ int gA[32], gB[32], cA[32], cB[32];

    int tx = threadIdx.x, ty = threadIdx.y;
    if (ty == 0) {
        int a = bi * 32 + tx;
        int va = (a < n) ? d_act[a] : -1;
        gA[tx] = va; cA[tx] = (va >= 0) ? d_cls[va] : 0;
        int b = bj * 32 + tx;
        int vb = (b < n) ? d_act[b] : -1;
        gB[tx] = vb; cB[tx] = (vb >= 0) ? d_cls[vb] : 0;
    }
    __syncthreads();

    int va = gA[ty], vb = gB[tx];
    float x = (va >= 0 && vb >= 0) ? con[(size_t)va * L + vb] : 0.0f;      // row va gather
    int vy = gB[ty], vxa = gA[tx];
    sT[ty][tx] = (vy >= 0 && vxa >= 0) ? con[(size_t)vy * L + vxa] : 0.0f; // row vb gather
    __syncthreads();

    float v = 0.5f * (x + sT[tx][ty]);         // con[va][vb] + con[vb][va]
    int a = bi * 32 + ty, b = bj * 32 + tx;
    float s = 0.0f;
    unsigned long long p = 0ULL;
    if (va >= 0 && vb >= 0) {
        int d = va - vb;
        bool band = (d >= 4) || (d <= -4);
        bool pm = (PAIRMASK >> ((cA[ty] << 2) | cB[tx])) & 1u;
        s = (band && pm) ? v : 0.0f;
        if (s > 0.0f && b > a) p = pack_l(s, a, b);
    }
    if (a < n && b < n) d_C[(size_t)a * ns + b] = s;
    __syncthreads();
    sT[ty][tx] = s;                             // reuse for transpose write
    sP[ty][tx] = p;
    __syncthreads();

    int a2 = bj * 32 + ty, b2 = bi * 32 + tx;   // transposed tile, coalesced
    if (a2 < n && b2 < n) d_C[(size_t)a2 * ns + b2] = sT[tx][ty];

    unsigned long long m = warp_max(p);                 // row max -> local a
    if (tx == 0 && m) atomicMax(&d_best[a], m);
    unsigned long long cm = warp_max(sP[tx][ty]);       // col max -> local bj*32+ty
    if (tx == 0 && cm) atomicMax(&d_best[bj * 32 + ty], cm);
}

// ---------------- K5: local-space take (1 block) ----------------
// srcSel < 0: identity list 0..d_nAct
__global__ void kern_takeL(int srcSel, int dstSel, float* __restrict__ out) {
    __shared__ int wsum[32];
    __shared__ int sTotal;
    int t = threadIdx.x;
    int lane = t & 31, wid = t >> 5;
    int n = (srcSel < 0) ? d_nAct : d_nL[srcSel];
    const int* lst = (srcSel < 0) ? 0 : d_lact[srcSel];

    int f[2]; int vv[2];
    #pragma unroll
    for (int r = 0; r < 2; r++) {
        int idx = 2 * t + r;
        int fl = 0, la = -1;
        if (idx < n) {
            la = lst ? lst[idx] : idx;
            unsigned long long b = d_best[la];
            if (b) {
                unsigned k = ~((unsigned)b);
                int lo = (int)(k >> LSHIFT), hi = (int)(k & LMASK);
                int lu = (la == lo) ? hi : lo;
                if (d_best[lu] == b) {
                    if (la == lo) {
                        float val = __uint_as_float((unsigned)(b >> 32));
                        int gi = d_act[lo], gj = d_act[hi];
                        out[gi * L + gj] = val;
                        out[gj * L + gi] = val;
                    }
                } else fl = 1;
            }
        }
        f[r] = fl; vv[r] = la;
    }

    int sum = f[0] + f[1];
    int x = sum;
    #pragma unroll
    for (int o = 1; o < 32; o <<= 1) { int y = __shfl_up_sync(0xFFFFFFFFu, x, o); if (lane >= o) x += y; }
    if (lane == 31) wsum[wid] = x;
    __syncthreads();
    if (wid == 0) {
        int z = wsum[lane];
        #pragma unroll
        for (int o = 1; o < 32; o <<= 1) { int y = __shfl_up_sync(0xFFFFFFFFu, z, o); if (lane >= o) z += y; }
        wsum[lane] = z;
        if (lane == 31) sTotal = z;
    }
    __syncthreads();
    int ex = (wid ? wsum[wid - 1] : 0) + x - sum;
    if (f[0]) d_lact[dstSel][ex] = vv[0];
    if (f[1]) d_lact[dstSel][ex + f[0]] = vv[1];
    if (t == 0) d_nL[dstSel] = sTotal;
}

// ---------------- K6: local-space best over C (multi-CTA, warp per row) ----------------
__global__ void kern_bestL(int sel) {
    __shared__ int sAct[L];
    int n = d_nL[sel];
    if (n == 0) return;
    int ns = (d_nAct + 31) & ~31;
    const int* lst = d_lact[sel];
    for (int t = threadIdx.x; t < n; t += blockDim.x) sAct[t] = lst[t];
    __syncthreads();

    int lane = threadIdx.x & 31;
    int gw = (blockIdx.x * blockDim.x + threadIdx.x) >> 5;
    int tw = (gridDim.x * blockDim.x) >> 5;

    for (int a = gw; a < n; a += tw) {
        int la = sAct[a];
        const float* __restrict__ row = d_C + (size_t)la * ns;
        unsigned long long m = 0ULL;
        for (int l = lane; l < n; l += 32) {
            int lb = sAct[l];
            float s = row[lb];
            if (s > 0.0f) {
                unsigned long long p = (la < lb) ? pack_l(s, la, lb) : pack_l(s, lb, la);
                if (p > m) m = p;
            }
        }
        m = warp_max(m);
        if (lane == 0) d_best[la] = m;
    }
}

// ---------------- K7: persistent single block — tail rounds (n small) ----------------
__global__ void kern_finish(int sel, float* __restrict__ out) {
    __shared__ int sG[L];                      // local -> global id
    __shared__ int sCur[L];                    // current local ids
    __shared__ int sTmp[L];
    __shared__ unsigned long long sBest[L];    // indexed by local id
    __shared__ int wsum[32];
    __shared__ int sTotal;

    int t = threadIdx.x;                       // 1024 threads
    int lane = t & 31, wid = t >> 5;
    int n0 = d_nAct;
    int ns = (n0 + 31) & ~31;
    int n = d_nL[sel];

    for (int x = t; x < n0; x += 1024) {
        sG[x] = d_act[x];
        sBest[x] = d_best[x];
    }
    for (int x = t; x < n; x += 1024) sCur[x] = d_lact[sel][x];
    __syncthreads();

    while (n > 0) {
        // ---- take: mutual-best edges over sCur ----
        int f[2]; int vv[2];
        #pragma unroll
        for (int r = 0; r < 2; r++) {
            int idx = 2 * t + r;
            int fl = 0, la = -1;
            if (idx < n) {
                la = sCur[idx];
                unsigned long long b = sBest[la];
                if (b) {
                    unsigned k = ~((unsigned)b);
                    int lo = (int)(k >> LSHIFT), hi = (int)(k & LMASK);
                    int lu = (la == lo) ? hi : lo;
                    if (sBest[lu] == b) {
                        if (la == lo) {
                            float val = __uint_as_float((unsigned)(b >> 32));
                            int gi = sG[lo], gj = sG[hi];
                            out[gi * L + gj] = val;
                            out[gj * L + gi] = val;
                        }
                    } else fl = 1;
                }
            }
            f[r] = fl; vv[r] = la;
        }

        // ---- compact survivors ----
        int sum = f[0] + f[1];
        int x = sum;
        #pragma unroll
        for (int o = 1; o < 32; o <<= 1) { int y = __shfl_up_sync(0xFFFFFFFFu, x, o); if (lane >= o) x += y; }
        if (lane == 31) wsum[wid] = x;
        __syncthreads();
        if (wid == 0) {
            int z = wsum[lane];
            #pragma unroll
            for (int o = 1; o < 32; o <<= 1) { int y = __shfl_up_sync(0xFFFFFFFFu, z, o); if (lane >= o) z += y; }
            wsum[lane] = z;
            if (lane == 31) sTotal = z;
        }
        __syncthreads();
        int ex = (wid ? wsum[wid - 1] : 0) + x - sum;
        if (f[0]) sTmp[ex] = vv[0];
        if (f[1]) sTmp[ex + f[0]] = vv[1];
        __syncthreads();
        int nn = sTotal;
        for (int x2 = t; x2 < nn; x2 += 1024) sCur[x2] = sTmp[x2];
        __syncthreads();
        n = nn;
        if (n == 0) break;

        // ---- recompute best over current set (warp per row, L2-resident C) ----
        for (int ai = wid; ai < n; ai += 32) {
            int la = sCur[ai];
            const float* __restrict__ row = d_C + (size_t)la * ns;
            unsigned long long m = 0ULL;
            for (int li = lane; li < n; li += 32) {
                int lb = sCur[li];
                float s = row[lb];
                if (s > 0.0f) {
                    unsigned long long p = (la < lb) ? pack_l(s, la, lb) : pack_l(s, lb, la);
                    if (p > m) m = p;
                }
            }
            m = warp_max(m);
            if (lane == 0) sBest[la] = m;
        }
        __syncthreads();
    }
}

// ---------------- launch ----------------
extern "C" void kernel_launch(void* const* d_in, const int* in_sizes, int n_in,
                              void* d_out, int out_size) {
    const float* con  = (const float*)d_in[0];
    const float* feat = (const float*)d_in[1];
    if (n_in >= 2 && in_sizes[0] > in_sizes[1]) {   // feat (8L^2) is the bigger input
        const float* tmp = con; con = feat; feat = tmp;
    }
    float* out = (float*)d_out;

    kern_cls<<<2, 1024>>>(feat);

    dim3 gb(L / 32, L / 32), tb(32, 32);
    kern_build<<<gb, tb>>>(con, out);        // round-1 best + output zeroing fused

    kern_take1<<<1, 1024>>>(out);            // round-1 take -> d_act, clears d_best

    kern_compact<<<gb, tb>>>(con);           // gather C + round-2 best fused

    // rounds 2..5: multi-CTA best + 1-block take, local index space
    kern_takeL<<<1, 1024>>>(-1, 0, out);     // take round 2 (identity list)
    kern_bestL<<<64, 1024>>>(0);             // best round 3
    kern_takeL<<<1, 1024>>>(0, 1, out);      // take round 3
    kern_bestL<<<64, 1024>>>(1);             // best round 4
    kern_takeL<<<1, 1024>>>(1, 0, out);      // take round 4
    kern_bestL<<<64, 1024>>>(0);             // best round 5
    kern_takeL<<<1, 1024>>>(0, 1, out);      // take round 5
    kern_bestL<<<64, 1024>>>(1);             // best round 6

    kern_finish<<<1, 1024>>>(1, out);        // tail rounds (n small)
}